// round 1
// baseline (speedup 1.0000x reference)
#include <cuda_runtime.h>
#include <cstdint>

#define N_SRC_MAX 100000
#define N_DST_MAX 50000
#define E_MAX     1250000
#define F         64

// Scratch (device globals; no allocation allowed)
__device__ float g_neigh[N_DST_MAX * F];   // segment-sum accumulator
__device__ float g_hu[N_SRC_MAX];
__device__ float g_coef[N_SRC_MAX];        // norm_deg_src / q_probs / E
__device__ float g_hv[N_DST_MAX];
__device__ float g_att[E_MAX];

// ---------------------------------------------------------------------------
// Kernel 0: zero the neigh accumulator (float4 stores)
// ---------------------------------------------------------------------------
__global__ void zero_neigh_kernel(int n_dst) {
    int total4 = n_dst * (F / 4);
    int i = blockIdx.x * blockDim.x + threadIdx.x;
    if (i < total4) {
        ((float4*)g_neigh)[i] = make_float4(0.f, 0.f, 0.f, 0.f);
    }
}

// ---------------------------------------------------------------------------
// Kernel 1: per-node projections. One warp per node (src nodes first, then dst).
//   hu[i]   = node_feat_src[i,:] . sample_weights[:,0]
//   coef[i] = norm_deg_src[i] / q_probs[i] / E
//   hv[j]   = node_feat_dst[j,:] . sample_weights[:,1]
// ---------------------------------------------------------------------------
__global__ void node_proj_kernel(const float* __restrict__ nfs,
                                 const float* __restrict__ nfd,
                                 const float* __restrict__ nds,
                                 const float* __restrict__ q,
                                 const float* __restrict__ sw,  // [64,2] row-major
                                 int n_src, int n_dst, float inv_e) {
    int warp = (blockIdx.x * blockDim.x + threadIdx.x) >> 5;
    int lane = threadIdx.x & 31;
    if (warp < n_src) {
        int i = warp;
        float v = nfs[i * F + lane]      * sw[lane * 2]
                + nfs[i * F + 32 + lane] * sw[(lane + 32) * 2];
        #pragma unroll
        for (int o = 16; o; o >>= 1) v += __shfl_xor_sync(0xFFFFFFFFu, v, o);
        if (lane == 0) {
            g_hu[i]   = v;
            g_coef[i] = nds[i] / q[i] * inv_e;
        }
    } else if (warp < n_src + n_dst) {
        int i = warp - n_src;
        float v = nfd[i * F + lane]      * sw[lane * 2 + 1]
                + nfd[i * F + 32 + lane] * sw[(lane + 32) * 2 + 1];
        #pragma unroll
        for (int o = 16; o; o >>= 1) v += __shfl_xor_sync(0xFFFFFFFFu, v, o);
        if (lane == 0) g_hv[i] = v;
    }
}

// ---------------------------------------------------------------------------
// Kernel 2: per-edge attention scalar (coalesced idx reads, L2-resident gathers)
//   att[e] = coef[s] * ndd[d] * (relu(hu[s]+hv[d]) + 0.1)
// ---------------------------------------------------------------------------
__global__ void att_kernel(const int* __restrict__ src_idx,
                           const int* __restrict__ dst_idx,
                           const float* __restrict__ ndd,
                           int n_edges) {
    int e = blockIdx.x * blockDim.x + threadIdx.x;
    if (e < n_edges) {
        int s = src_idx[e];
        int d = dst_idx[e];
        float a = g_coef[s] * ndd[d] * (fmaxf(g_hu[s] + g_hv[d], 0.f) + 0.1f);
        g_att[e] = a;
    }
}

// ---------------------------------------------------------------------------
// Kernel 3: scatter. 16 threads per edge, each handles one float4 (4 feats).
//   neigh[d,:] += hidden_feat[s,:] * att[e]     via red.global.add.v4.f32
// ---------------------------------------------------------------------------
__global__ void scatter_kernel(const float* __restrict__ hidden,
                               const int* __restrict__ src_idx,
                               const int* __restrict__ dst_idx,
                               int n_edges) {
    int t = blockIdx.x * blockDim.x + threadIdx.x;
    int e = t >> 4;
    int qd = t & 15;
    if (e < n_edges) {
        float a = g_att[e];
        int s = src_idx[e];
        int d = dst_idx[e];
        float4 h = ((const float4*)hidden)[s * (F / 4) + qd];
        float4 m = make_float4(h.x * a, h.y * a, h.z * a, h.w * a);
        float* p = &g_neigh[d * F + qd * 4];
        asm volatile("red.global.add.v4.f32 [%0], {%1,%2,%3,%4};"
                     :: "l"(p), "f"(m.x), "f"(m.y), "f"(m.z), "f"(m.w)
                     : "memory");
    }
}

// ---------------------------------------------------------------------------
// Kernel 4: FC epilogue. rst = neigh @ fc_weight^T + fc_bias
// One block handles 16 dst rows; fc_weight transposed into smem (conflict-free).
// 256 threads: c = tid&63, 4 rows per thread.
// ---------------------------------------------------------------------------
#define FC_ROWS 16
__global__ void fc_kernel(const float* __restrict__ fcw,  // [64,64] row-major
                          const float* __restrict__ bias,
                          float* __restrict__ out, int n_dst) {
    __shared__ float fwT[F * F];       // fwT[k*64 + c] = fcw[c*64 + k]
    __shared__ float ns[FC_ROWS * F];
    int tid = threadIdx.x;
    for (int j = tid; j < F * F; j += 256)
        fwT[(j & 63) * F + (j >> 6)] = fcw[j];
    int row0 = blockIdx.x * FC_ROWS;
    for (int j = tid; j < FC_ROWS * F; j += 256) {
        int r = row0 + (j >> 6);
        ns[j] = (r < n_dst) ? g_neigh[r * F + (j & 63)] : 0.f;
    }
    __syncthreads();

    int c  = tid & 63;
    int r0 = tid >> 6;           // 0..3
    float b = bias[c];
    float acc0 = b, acc1 = b, acc2 = b, acc3 = b;
    #pragma unroll
    for (int k = 0; k < F; k++) {
        float w = fwT[k * F + c];
        acc0 += ns[(r0 + 0) * F + k]  * w;
        acc1 += ns[(r0 + 4) * F + k]  * w;
        acc2 += ns[(r0 + 8) * F + k]  * w;
        acc3 += ns[(r0 + 12) * F + k] * w;
    }
    int r;
    r = row0 + r0 + 0;  if (r < n_dst) out[r * F + c] = acc0;
    r = row0 + r0 + 4;  if (r < n_dst) out[r * F + c] = acc1;
    r = row0 + r0 + 8;  if (r < n_dst) out[r * F + c] = acc2;
    r = row0 + r0 + 12; if (r < n_dst) out[r * F + c] = acc3;
}

// ---------------------------------------------------------------------------
// Launch
// ---------------------------------------------------------------------------
extern "C" void kernel_launch(void* const* d_in, const int* in_sizes, int n_in,
                              void* d_out, int out_size) {
    const float* hidden_feat   = (const float*)d_in[0];
    const float* node_feat_src = (const float*)d_in[1];
    const float* node_feat_dst = (const float*)d_in[2];
    const float* norm_deg_src  = (const float*)d_in[3];
    const float* norm_deg_dst  = (const float*)d_in[4];
    const float* q_probs       = (const float*)d_in[5];
    const float* sample_w      = (const float*)d_in[6];
    const float* fc_weight     = (const float*)d_in[7];
    const float* fc_bias       = (const float*)d_in[8];
    const int*   src_idx       = (const int*)d_in[9];
    const int*   dst_idx       = (const int*)d_in[10];

    int n_src   = in_sizes[3];
    int n_dst   = in_sizes[4];
    int n_edges = in_sizes[9];
    if (n_src > N_SRC_MAX) n_src = N_SRC_MAX;
    if (n_dst > N_DST_MAX) n_dst = N_DST_MAX;
    if (n_edges > E_MAX)   n_edges = E_MAX;

    float* out = (float*)d_out;
    float inv_e = 1.0f / (float)n_edges;

    // 0: zero accumulator
    {
        int total4 = n_dst * (F / 4);
        zero_neigh_kernel<<<(total4 + 255) / 256, 256>>>(n_dst);
    }
    // 1: node projections (one warp per node)
    {
        int warps = n_src + n_dst;
        int blocks = (warps * 32 + 255) / 256;
        node_proj_kernel<<<blocks, 256>>>(node_feat_src, node_feat_dst,
                                          norm_deg_src, q_probs, sample_w,
                                          n_src, n_dst, inv_e);
    }
    // 2: per-edge attention
    att_kernel<<<(n_edges + 255) / 256, 256>>>(src_idx, dst_idx,
                                               norm_deg_dst, n_edges);
    // 3: scatter (16 threads / edge)
    {
        long long total = (long long)n_edges * 16;
        int blocks = (int)((total + 255) / 256);
        scatter_kernel<<<blocks, 256>>>(hidden_feat, src_idx, dst_idx, n_edges);
    }
    // 4: FC epilogue
    fc_kernel<<<(n_dst + FC_ROWS - 1) / FC_ROWS, 256>>>(fc_weight, fc_bias,
                                                        out, n_dst);
}